// round 1
// baseline (speedup 1.0000x reference)
#include <cuda_runtime.h>

#define N_NODES   20000
#define N_EDGES   640000
#define BASIS     128
#define NUM_GAUSS 64
#define HIDDEN    256
#define NUM_GRAPHS 256

// ---------------- scratch (device globals: allocation-free rule) ----------------
__device__ float g_dfeat[(size_t)N_EDGES * BASIS];   // 327 MB, iteration-invariant
__device__ float g_C[2][(size_t)N_NODES * BASIS];    // ping-pong node states
__device__ float g_Cc[(size_t)N_NODES * BASIS];      // per-iter node transform

// fast tanh: (e^{2x}-1)/(e^{2x}+1) with clamp, EX2/RCP based
__device__ __forceinline__ float fast_tanh(float x) {
    float xc = fminf(fmaxf(x, -9.0f), 9.0f);
    float e  = __expf(2.0f * xc);
    return __fdividef(e - 1.0f, e + 1.0f);
}

// ---------------- K0: zero output ----------------
__global__ void k_zero(float* __restrict__ out) {
    ((float4*)out)[threadIdx.x] = make_float4(0.f, 0.f, 0.f, 0.f);
}

// ---------------- K1: C0 = embed[Z] ----------------
__global__ __launch_bounds__(256) void k_init(const int* __restrict__ Z,
                                              const float* __restrict__ embed) {
    int idx = blockIdx.x * 256 + threadIdx.x;   // float4 index over N_NODES*32
    int v = idx >> 5, c4 = idx & 31;
    float4 val = ((const float4*)embed)[(size_t)Z[v] * 32 + c4];
    ((float4*)g_C[0])[idx] = val;
}

// ---------------- K2: d_feat = edge_attr @ dfW.T + dfb  [E,128] ----------------
// 64 edges/block, 256 threads, microtile 8 edges x 4 outs, K=64
__global__ __launch_bounds__(256) void k_dfeat(const float* __restrict__ edge_attr,
                                               const float* __restrict__ dfW,
                                               const float* __restrict__ dfb) {
    extern __shared__ float sm[];
    float* sW = sm;                  // [128][64]
    float* sA = sm + 128 * 64;       // [64][68] padded
    float* sB = sA + 64 * 68;        // [128]
    int t = threadIdx.x;
    int e0 = blockIdx.x * 64;

    for (int i = t; i < 2048; i += 256)
        ((float4*)sW)[i] = ((const float4*)dfW)[i];
    if (t < 128) sB[t] = dfb[t];
    for (int i = t; i < 64 * 16; i += 256) {
        int e = i >> 4, g4 = i & 15;
        float4 v = ((const float4*)edge_attr)[(size_t)(e0 + e) * 16 + g4];
        *(float4*)&sA[e * 68 + g4 * 4] = v;
    }
    __syncthreads();

    int tx = t & 7, ty = t >> 3;     // edges tx+8*ii, outs ty*4+jj
    float acc[8][4];
#pragma unroll
    for (int ii = 0; ii < 8; ii++)
#pragma unroll
        for (int jj = 0; jj < 4; jj++) acc[ii][jj] = 0.f;

#pragma unroll 4
    for (int k = 0; k < 64; k += 4) {
        float4 av[8], wv[4];
#pragma unroll
        for (int ii = 0; ii < 8; ii++) av[ii] = *(float4*)&sA[(tx + 8 * ii) * 68 + k];
#pragma unroll
        for (int jj = 0; jj < 4; jj++) wv[jj] = *(float4*)&sW[(ty * 4 + jj) * 64 + k];
#pragma unroll
        for (int ii = 0; ii < 8; ii++)
#pragma unroll
            for (int jj = 0; jj < 4; jj++) {
                acc[ii][jj] = fmaf(av[ii].x, wv[jj].x, acc[ii][jj]);
                acc[ii][jj] = fmaf(av[ii].y, wv[jj].y, acc[ii][jj]);
                acc[ii][jj] = fmaf(av[ii].z, wv[jj].z, acc[ii][jj]);
                acc[ii][jj] = fmaf(av[ii].w, wv[jj].w, acc[ii][jj]);
            }
    }
    float4 bb = *(float4*)&sB[ty * 4];
#pragma unroll
    for (int ii = 0; ii < 8; ii++) {
        float4 o = make_float4(acc[ii][0] + bb.x, acc[ii][1] + bb.y,
                               acc[ii][2] + bb.z, acc[ii][3] + bb.w);
        ((float4*)g_dfeat)[(size_t)(e0 + tx + 8 * ii) * 32 + ty] = o;
    }
}

// ---------------- K3: Cc = C@cfW.T + cfb ; C2 = C ----------------
// 32 nodes/block, 256 threads, microtile 4x4
__global__ __launch_bounds__(256) void k_node(const float* __restrict__ cfW,
                                              const float* __restrict__ cfb,
                                              int sb) {
    extern __shared__ float sm[];
    float* sW = sm;                  // [128][128]
    float* sC = sm + 16384;          // [32][132]
    float* sBb = sC + 32 * 132;      // [128]
    const float* C = g_C[sb];
    float* C2 = g_C[sb ^ 1];
    int t = threadIdx.x, n0 = blockIdx.x * 32;

    for (int i = t; i < 4096; i += 256)
        ((float4*)sW)[i] = ((const float4*)cfW)[i];
    if (t < 128) sBb[t] = cfb[t];
    for (int i = t; i < 32 * 32; i += 256) {
        int n = i >> 5, c4 = i & 31;
        *(float4*)&sC[n * 132 + c4 * 4] = ((const float4*)C)[(size_t)(n0 + n) * 32 + c4];
    }
    __syncthreads();

    int tx = t & 7, ty = t >> 3;     // nodes tx+8*ii, outs ty*4+jj
    float acc[4][4];
#pragma unroll
    for (int ii = 0; ii < 4; ii++)
#pragma unroll
        for (int jj = 0; jj < 4; jj++) acc[ii][jj] = 0.f;

#pragma unroll 4
    for (int k = 0; k < 128; k += 4) {
        float4 cv[4], wv[4];
#pragma unroll
        for (int ii = 0; ii < 4; ii++) cv[ii] = *(float4*)&sC[(tx + 8 * ii) * 132 + k];
#pragma unroll
        for (int jj = 0; jj < 4; jj++) wv[jj] = *(float4*)&sW[(ty * 4 + jj) * 128 + k];
#pragma unroll
        for (int ii = 0; ii < 4; ii++)
#pragma unroll
            for (int jj = 0; jj < 4; jj++) {
                acc[ii][jj] = fmaf(cv[ii].x, wv[jj].x, acc[ii][jj]);
                acc[ii][jj] = fmaf(cv[ii].y, wv[jj].y, acc[ii][jj]);
                acc[ii][jj] = fmaf(cv[ii].z, wv[jj].z, acc[ii][jj]);
                acc[ii][jj] = fmaf(cv[ii].w, wv[jj].w, acc[ii][jj]);
            }
    }
    float4 bb = *(float4*)&sBb[ty * 4];
#pragma unroll
    for (int ii = 0; ii < 4; ii++) {
        float4 o = make_float4(acc[ii][0] + bb.x, acc[ii][1] + bb.y,
                               acc[ii][2] + bb.z, acc[ii][3] + bb.w);
        ((float4*)g_Cc)[(size_t)(n0 + tx + 8 * ii) * 32 + ty] = o;
    }
    // copy C -> C2 (scatter target base)
    for (int i = t; i < 32 * 32; i += 256) {
        int n = i >> 5, c4 = i & 31;
        ((float4*)C2)[(size_t)(n0 + n) * 32 + c4] = *(float4*)&sC[n * 132 + c4 * 4];
    }
}

// ---------------- K4 (hot): m = tanh((Cc[src]*d_feat)@fcW.T); C2[dst] += m ------
// 128 edges/block, 256 threads, microtile 8x8 (reuse 8 balances smem crossbar)
#define TE  128
#define PST 132
__global__ __launch_bounds__(256) void k_edge(const int* __restrict__ edge_index,
                                              const float* __restrict__ fcW,
                                              int db) {
    extern __shared__ float sm[];
    float* sW = sm;                   // [128][128]
    float* sP = sm + 16384;           // [128][132]
    int* sSrc = (int*)(sP + TE * PST);
    int* sDst = sSrc + TE;
    float* C2 = g_C[db];
    int t = threadIdx.x, e0 = blockIdx.x * TE;

    for (int i = t; i < 4096; i += 256)
        ((float4*)sW)[i] = ((const float4*)fcW)[i];
    if (t < TE)             sSrc[t]      = edge_index[e0 + t];
    else if (t < 2 * TE)    sDst[t - TE] = edge_index[N_EDGES + e0 + (t - TE)];
    __syncthreads();

    // build P = Cc[src] * d_feat  (d_feat coalesced from HBM, Cc gather hits L2)
    for (int i = t; i < TE * 32; i += 256) {
        int e = i >> 5, c4 = i & 31;
        float4 d = ((const float4*)g_dfeat)[(size_t)(e0 + e) * 32 + c4];
        float4 c = ((const float4*)g_Cc)[(size_t)sSrc[e] * 32 + c4];
        *(float4*)&sP[e * PST + c4 * 4] =
            make_float4(d.x * c.x, d.y * c.y, d.z * c.z, d.w * c.w);
    }
    __syncthreads();

    int tx = t & 15, ty = t >> 4;    // edges tx+16*ii (strided: conflict-free), outs ty+16*jj
    float acc[8][8];
#pragma unroll
    for (int ii = 0; ii < 8; ii++)
#pragma unroll
        for (int jj = 0; jj < 8; jj++) acc[ii][jj] = 0.f;

#pragma unroll 2
    for (int k = 0; k < 128; k += 4) {
        float4 pv[8], wv[8];
#pragma unroll
        for (int ii = 0; ii < 8; ii++) pv[ii] = *(float4*)&sP[(tx + 16 * ii) * PST + k];
#pragma unroll
        for (int jj = 0; jj < 8; jj++) wv[jj] = *(float4*)&sW[(ty + 16 * jj) * 128 + k];
#pragma unroll
        for (int ii = 0; ii < 8; ii++)
#pragma unroll
            for (int jj = 0; jj < 8; jj++) {
                acc[ii][jj] = fmaf(pv[ii].x, wv[jj].x, acc[ii][jj]);
                acc[ii][jj] = fmaf(pv[ii].y, wv[jj].y, acc[ii][jj]);
                acc[ii][jj] = fmaf(pv[ii].z, wv[jj].z, acc[ii][jj]);
                acc[ii][jj] = fmaf(pv[ii].w, wv[jj].w, acc[ii][jj]);
            }
    }
    __syncthreads();                 // all reads of sP done
    // tanh, stage back to sP
#pragma unroll
    for (int ii = 0; ii < 8; ii++)
#pragma unroll
        for (int jj = 0; jj < 8; jj++)
            sP[(tx + 16 * ii) * PST + (ty + 16 * jj)] = fast_tanh(acc[ii][jj]);
    __syncthreads();
    // scatter-add into C2[dst]
    for (int i = t; i < TE * 32; i += 256) {
        int e = i >> 5, c4 = i & 31;
        float4 v = *(float4*)&sP[e * PST + c4 * 4];
        float* ptr = C2 + (size_t)sDst[e] * BASIS + c4 * 4;
        atomicAdd(ptr + 0, v.x);
        atomicAdd(ptr + 1, v.y);
        atomicAdd(ptr + 2, v.z);
        atomicAdd(ptr + 3, v.w);
    }
}

// ---------------- K5: readout + pool ----------------
// h = tanh(C@r1W.T + r1b)@r2W.T + r2b; out[batch] += h
__global__ __launch_bounds__(256) void k_readout(const float* __restrict__ r1W,
                                                 const float* __restrict__ r1b,
                                                 const float* __restrict__ r2W,
                                                 const float* __restrict__ r2b,
                                                 const int* __restrict__ batch,
                                                 float* __restrict__ out, int sb) {
    extern __shared__ float sm[];
    float* sW1 = sm;                   // [256][128]
    float* sC  = sW1 + 32768;          // [32][132]
    float* sW2 = sC + 32 * 132;        // [4][256]
    float* sB1 = sW2 + 1024;           // [256]
    float* sAcc = sB1 + 256;           // [32][4]
    int*   sBat = (int*)(sAcc + 128);  // [32]
    const float* C = g_C[sb];
    int t = threadIdx.x, n0 = blockIdx.x * 32;

    for (int i = t; i < 8192; i += 256)
        ((float4*)sW1)[i] = ((const float4*)r1W)[i];
    if (t < 256) ((float4*)sW2)[t] = ((const float4*)r2W)[t];
    sB1[t] = r1b[t];
    if (t < 128) sAcc[t] = 0.f;
    if (t < 32)  sBat[t] = batch[n0 + t];
    for (int i = t; i < 32 * 32; i += 256) {
        int n = i >> 5, c4 = i & 31;
        *(float4*)&sC[n * 132 + c4 * 4] = ((const float4*)C)[(size_t)(n0 + n) * 32 + c4];
    }
    __syncthreads();

    int tx = t & 7, ty = t >> 3;     // nodes tx+8*ii, hidden ty*8+jj
    float acc[4][8];
#pragma unroll
    for (int ii = 0; ii < 4; ii++)
#pragma unroll
        for (int jj = 0; jj < 8; jj++) acc[ii][jj] = 0.f;

#pragma unroll 2
    for (int c = 0; c < 128; c += 4) {
        float4 cv[4], wv[8];
#pragma unroll
        for (int ii = 0; ii < 4; ii++) cv[ii] = *(float4*)&sC[(tx + 8 * ii) * 132 + c];
#pragma unroll
        for (int jj = 0; jj < 8; jj++) wv[jj] = *(float4*)&sW1[(ty * 8 + jj) * 128 + c];
#pragma unroll
        for (int ii = 0; ii < 4; ii++)
#pragma unroll
            for (int jj = 0; jj < 8; jj++) {
                acc[ii][jj] = fmaf(cv[ii].x, wv[jj].x, acc[ii][jj]);
                acc[ii][jj] = fmaf(cv[ii].y, wv[jj].y, acc[ii][jj]);
                acc[ii][jj] = fmaf(cv[ii].z, wv[jj].z, acc[ii][jj]);
                acc[ii][jj] = fmaf(cv[ii].w, wv[jj].w, acc[ii][jj]);
            }
    }
    // second linear (HIDDEN->4) with per-node bias added exactly once (ty==0)
    float po[4][4];
#pragma unroll
    for (int ii = 0; ii < 4; ii++)
#pragma unroll
        for (int o = 0; o < 4; o++) po[ii][o] = (ty == 0) ? r2b[o] : 0.f;
#pragma unroll
    for (int ii = 0; ii < 4; ii++)
#pragma unroll
        for (int jj = 0; jj < 8; jj++) {
            float h = fast_tanh(acc[ii][jj] + sB1[ty * 8 + jj]);
#pragma unroll
            for (int o = 0; o < 4; o++)
                po[ii][o] = fmaf(h, sW2[o * 256 + ty * 8 + jj], po[ii][o]);
        }
#pragma unroll
    for (int ii = 0; ii < 4; ii++)
#pragma unroll
        for (int o = 0; o < 4; o++)
            atomicAdd(&sAcc[(tx + 8 * ii) * 4 + o], po[ii][o]);
    __syncthreads();
    if (t < 128) {
        int n = t >> 2, o = t & 3;
        atomicAdd(&out[(size_t)sBat[n] * 4 + o], sAcc[t]);
    }
}

// ---------------- launch ----------------
extern "C" void kernel_launch(void* const* d_in, const int* in_sizes, int n_in,
                              void* d_out, int out_size) {
    const int*   Z         = (const int*)d_in[0];
    const int*   edge_index= (const int*)d_in[1];
    const float* edge_attr = (const float*)d_in[2];
    const int*   batch     = (const int*)d_in[3];
    const float* embed     = (const float*)d_in[4];
    const float* cfW       = (const float*)d_in[5];
    const float* cfb       = (const float*)d_in[6];
    const float* dfW       = (const float*)d_in[7];
    const float* dfb       = (const float*)d_in[8];
    const float* fcW       = (const float*)d_in[9];
    const float* r1W       = (const float*)d_in[10];
    const float* r1b       = (const float*)d_in[11];
    const float* r2W       = (const float*)d_in[12];
    const float* r2b       = (const float*)d_in[13];
    float* out = (float*)d_out;

    const int smK2 = (128 * 64 + 64 * 68 + 128) * 4;                 // 50688
    const int smK3 = (16384 + 32 * 132 + 128) * 4;                   // 82944
    const int smK4 = (16384 + TE * PST) * 4 + 2 * TE * 4;            // 134144
    const int smK5 = (32768 + 32 * 132 + 1024 + 256 + 128) * 4 + 32 * 4; // 153728

    cudaFuncSetAttribute(k_dfeat,   cudaFuncAttributeMaxDynamicSharedMemorySize, smK2);
    cudaFuncSetAttribute(k_node,    cudaFuncAttributeMaxDynamicSharedMemorySize, smK3);
    cudaFuncSetAttribute(k_edge,    cudaFuncAttributeMaxDynamicSharedMemorySize, smK4);
    cudaFuncSetAttribute(k_readout, cudaFuncAttributeMaxDynamicSharedMemorySize, smK5);

    k_zero<<<1, 256>>>(out);
    k_init<<<(N_NODES * 32) / 256, 256>>>(Z, embed);
    k_dfeat<<<N_EDGES / 64, 256, smK2>>>(edge_attr, dfW, dfb);

    int sb = 0;
    for (int it = 0; it < 3; it++) {
        k_node<<<N_NODES / 32, 256, smK3>>>(cfW, cfb, sb);
        k_edge<<<N_EDGES / TE, 256, smK4>>>(edge_index, fcW, sb ^ 1);
        sb ^= 1;
    }
    k_readout<<<N_NODES / 32, 256, smK5>>>(r1W, r1b, r2W, r2b, batch, out, sb);
}

// round 2
// speedup vs baseline: 1.1780x; 1.1780x over previous
#include <cuda_runtime.h>
#include <cuda_bf16.h>
#include <cstdint>

#define N_NODES   20000
#define N_EDGES   640000
#define BASIS     128
#define NUM_GAUSS 64
#define HIDDEN    256
#define NUM_GRAPHS 256

// ---------------- scratch (device globals: allocation-free rule) ----------------
__device__ float g_dfeat[(size_t)N_EDGES * BASIS];   // 327 MB, iteration-invariant
__device__ float g_C[2][(size_t)N_NODES * BASIS];    // ping-pong node states
__device__ float g_Cc[(size_t)N_NODES * BASIS];      // per-iter node transform

// fast tanh: (e^{2x}-1)/(e^{2x}+1) with clamp, EX2/RCP based
__device__ __forceinline__ float fast_tanh(float x) {
    float xc = fminf(fmaxf(x, -9.0f), 9.0f);
    float e  = __expf(2.0f * xc);
    return __fdividef(e - 1.0f, e + 1.0f);
}

// Dekker split: x = hi(tf32) + lo, lo stored as bf16 (subset of tf32 after <<16)
__device__ __forceinline__ void split_tf32(float x, uint32_t& hi_bits, unsigned short& lo_bf16) {
    uint32_t hu;
    asm("cvt.rna.tf32.f32 %0, %1;" : "=r"(hu) : "f"(x));
    hi_bits = hu;
    float lo = x - __uint_as_float(hu);              // exact
    lo_bf16 = __bfloat16_as_ushort(__float2bfloat16_rn(lo));
}

#define MMA_TF32(D, a0, a1, a2, a3, b0, b1)                                   \
    asm volatile("mma.sync.aligned.m16n8k8.row.col.f32.tf32.tf32.f32 "         \
                 "{%0,%1,%2,%3}, {%4,%5,%6,%7}, {%8,%9}, {%0,%1,%2,%3};"       \
                 : "+f"((D)[0]), "+f"((D)[1]), "+f"((D)[2]), "+f"((D)[3])      \
                 : "r"(a0), "r"(a1), "r"(a2), "r"(a3), "r"(b0), "r"(b1))

// ---------------- K0: zero output ----------------
__global__ void k_zero(float* __restrict__ out) {
    ((float4*)out)[threadIdx.x] = make_float4(0.f, 0.f, 0.f, 0.f);
}

// ---------------- K1: C0 = embed[Z] ----------------
__global__ __launch_bounds__(256) void k_init(const int* __restrict__ Z,
                                              const float* __restrict__ embed) {
    int idx = blockIdx.x * 256 + threadIdx.x;
    int v = idx >> 5, c4 = idx & 31;
    float4 val = ((const float4*)embed)[(size_t)Z[v] * 32 + c4];
    ((float4*)g_C[0])[idx] = val;
}

// ---------------- K2: d_feat = edge_attr @ dfW.T + dfb  [E,128] ----------------
__global__ __launch_bounds__(256) void k_dfeat(const float* __restrict__ edge_attr,
                                               const float* __restrict__ dfW,
                                               const float* __restrict__ dfb) {
    extern __shared__ float sm[];
    float* sW = sm;                  // [128][64]
    float* sA = sm + 128 * 64;       // [64][68]
    float* sB = sA + 64 * 68;        // [128]
    int t = threadIdx.x;
    int e0 = blockIdx.x * 64;

    for (int i = t; i < 2048; i += 256)
        ((float4*)sW)[i] = ((const float4*)dfW)[i];
    if (t < 128) sB[t] = dfb[t];
    for (int i = t; i < 64 * 16; i += 256) {
        int e = i >> 4, g4 = i & 15;
        float4 v = ((const float4*)edge_attr)[(size_t)(e0 + e) * 16 + g4];
        *(float4*)&sA[e * 68 + g4 * 4] = v;
    }
    __syncthreads();

    int tx = t & 7, ty = t >> 3;
    float acc[8][4];
#pragma unroll
    for (int ii = 0; ii < 8; ii++)
#pragma unroll
        for (int jj = 0; jj < 4; jj++) acc[ii][jj] = 0.f;

#pragma unroll 4
    for (int k = 0; k < 64; k += 4) {
        float4 av[8], wv[4];
#pragma unroll
        for (int ii = 0; ii < 8; ii++) av[ii] = *(float4*)&sA[(tx + 8 * ii) * 68 + k];
#pragma unroll
        for (int jj = 0; jj < 4; jj++) wv[jj] = *(float4*)&sW[(ty * 4 + jj) * 64 + k];
#pragma unroll
        for (int ii = 0; ii < 8; ii++)
#pragma unroll
            for (int jj = 0; jj < 4; jj++) {
                acc[ii][jj] = fmaf(av[ii].x, wv[jj].x, acc[ii][jj]);
                acc[ii][jj] = fmaf(av[ii].y, wv[jj].y, acc[ii][jj]);
                acc[ii][jj] = fmaf(av[ii].z, wv[jj].z, acc[ii][jj]);
                acc[ii][jj] = fmaf(av[ii].w, wv[jj].w, acc[ii][jj]);
            }
    }
    float4 bb = *(float4*)&sB[ty * 4];
#pragma unroll
    for (int ii = 0; ii < 8; ii++) {
        float4 o = make_float4(acc[ii][0] + bb.x, acc[ii][1] + bb.y,
                               acc[ii][2] + bb.z, acc[ii][3] + bb.w);
        ((float4*)g_dfeat)[(size_t)(e0 + tx + 8 * ii) * 32 + ty] = o;
    }
}

// ---------------- K3: Cc = C@cfW.T + cfb ; C2 = C ----------------
__global__ __launch_bounds__(256) void k_node(const float* __restrict__ cfW,
                                              const float* __restrict__ cfb,
                                              int sb) {
    extern __shared__ float sm[];
    float* sW = sm;                  // [128][128]
    float* sC = sm + 16384;          // [32][132]
    float* sBb = sC + 32 * 132;      // [128]
    const float* C = g_C[sb];
    float* C2 = g_C[sb ^ 1];
    int t = threadIdx.x, n0 = blockIdx.x * 32;

    for (int i = t; i < 4096; i += 256)
        ((float4*)sW)[i] = ((const float4*)cfW)[i];
    if (t < 128) sBb[t] = cfb[t];
    for (int i = t; i < 32 * 32; i += 256) {
        int n = i >> 5, c4 = i & 31;
        *(float4*)&sC[n * 132 + c4 * 4] = ((const float4*)C)[(size_t)(n0 + n) * 32 + c4];
    }
    __syncthreads();

    int tx = t & 7, ty = t >> 3;
    float acc[4][4];
#pragma unroll
    for (int ii = 0; ii < 4; ii++)
#pragma unroll
        for (int jj = 0; jj < 4; jj++) acc[ii][jj] = 0.f;

#pragma unroll 4
    for (int k = 0; k < 128; k += 4) {
        float4 cv[4], wv[4];
#pragma unroll
        for (int ii = 0; ii < 4; ii++) cv[ii] = *(float4*)&sC[(tx + 8 * ii) * 132 + k];
#pragma unroll
        for (int jj = 0; jj < 4; jj++) wv[jj] = *(float4*)&sW[(ty * 4 + jj) * 128 + k];
#pragma unroll
        for (int ii = 0; ii < 4; ii++)
#pragma unroll
            for (int jj = 0; jj < 4; jj++) {
                acc[ii][jj] = fmaf(cv[ii].x, wv[jj].x, acc[ii][jj]);
                acc[ii][jj] = fmaf(cv[ii].y, wv[jj].y, acc[ii][jj]);
                acc[ii][jj] = fmaf(cv[ii].z, wv[jj].z, acc[ii][jj]);
                acc[ii][jj] = fmaf(cv[ii].w, wv[jj].w, acc[ii][jj]);
            }
    }
    float4 bb = *(float4*)&sBb[ty * 4];
#pragma unroll
    for (int ii = 0; ii < 4; ii++) {
        float4 o = make_float4(acc[ii][0] + bb.x, acc[ii][1] + bb.y,
                               acc[ii][2] + bb.z, acc[ii][3] + bb.w);
        ((float4*)g_Cc)[(size_t)(n0 + tx + 8 * ii) * 32 + ty] = o;
    }
    for (int i = t; i < 32 * 32; i += 256) {
        int n = i >> 5, c4 = i & 31;
        ((float4*)C2)[(size_t)(n0 + n) * 32 + c4] = *(float4*)&sC[n * 132 + c4 * 4];
    }
}

// ---------------- K4 (hot): m = tanh((Cc[src]*d_feat)@fcW.T); C2[dst] += m ------
// TF32 tensor-core GEMM with Dekker split (hi: tf32-in-f32, lo: bf16).
// TE=128 edges/block, 256 threads (8 warps), warp w owns edges [16w,16w+16).
#define TE   128
#define PADP 132
__global__ __launch_bounds__(256) void k_edge(const int* __restrict__ edge_index,
                                              const float* __restrict__ fcW,
                                              int db) {
    extern __shared__ float sm[];
    float*          sWhi = sm;                       // [128][132] f32 (tf32 vals)
    float*          sPhi = sm + 128 * PADP;          // [128][132] f32 (tf32 vals)
    unsigned short* sWlo = (unsigned short*)(sm + 2 * 128 * PADP); // [128][132] bf16
    unsigned short* sPlo = sWlo + 128 * PADP;        // [128][132] bf16
    int*            sSrc = (int*)(sPlo + 128 * PADP);
    int*            sDst = sSrc + TE;
    float* C2 = g_C[db];
    int t = threadIdx.x, e0 = blockIdx.x * TE;

    // ---- phase 1: stage & split W, load indices ----
    for (int i = t; i < 4096; i += 256) {            // i = float4 index over fcW
        int n = i >> 5, k4 = i & 31;
        float4 w = ((const float4*)fcW)[i];
        uint32_t h0, h1, h2, h3; unsigned short l0, l1, l2, l3;
        split_tf32(w.x, h0, l0); split_tf32(w.y, h1, l1);
        split_tf32(w.z, h2, l2); split_tf32(w.w, h3, l3);
        float4 hv = make_float4(__uint_as_float(h0), __uint_as_float(h1),
                                __uint_as_float(h2), __uint_as_float(h3));
        *(float4*)&sWhi[n * PADP + k4 * 4] = hv;
        uint2 lv = make_uint2((uint32_t)l0 | ((uint32_t)l1 << 16),
                              (uint32_t)l2 | ((uint32_t)l3 << 16));
        *(uint2*)&sWlo[n * PADP + k4 * 4] = lv;
    }
    if (t < TE)          sSrc[t]      = edge_index[e0 + t];
    else if (t < 2 * TE) sDst[t - TE] = edge_index[N_EDGES + e0 + (t - TE)];
    __syncthreads();

    // ---- phase 2: build & split P = Cc[src] * d_feat ----
    for (int i = t; i < TE * 32; i += 256) {
        int e = i >> 5, c4 = i & 31;
        float4 d = ((const float4*)g_dfeat)[(size_t)(e0 + e) * 32 + c4];
        float4 c = ((const float4*)g_Cc)[(size_t)sSrc[e] * 32 + c4];
        float4 p = make_float4(d.x * c.x, d.y * c.y, d.z * c.z, d.w * c.w);
        uint32_t h0, h1, h2, h3; unsigned short l0, l1, l2, l3;
        split_tf32(p.x, h0, l0); split_tf32(p.y, h1, l1);
        split_tf32(p.z, h2, l2); split_tf32(p.w, h3, l3);
        float4 hv = make_float4(__uint_as_float(h0), __uint_as_float(h1),
                                __uint_as_float(h2), __uint_as_float(h3));
        *(float4*)&sPhi[e * PADP + c4 * 4] = hv;
        uint2 lv = make_uint2((uint32_t)l0 | ((uint32_t)l1 << 16),
                              (uint32_t)l2 | ((uint32_t)l3 << 16));
        *(uint2*)&sPlo[e * PADP + c4 * 4] = lv;
    }
    __syncthreads();

    // ---- phase 3: tensor-core GEMM  D[128e x 128n] = P @ W^T ----
    const int lane = t & 31, wid = t >> 5;
    const int grp = lane >> 2, t4 = lane & 3;
    const int m0 = wid * 16 + grp;                   // warp's edge rows: m0, m0+8

    float acc[64];                                   // 16 n-tiles x 4 regs
#pragma unroll
    for (int i = 0; i < 64; i++) acc[i] = 0.f;

    const float*          phiR0 = sPhi + m0 * PADP;
    const float*          phiR1 = phiR0 + 8 * PADP;
    const unsigned short* ploR0 = sPlo + m0 * PADP;
    const unsigned short* ploR1 = ploR0 + 8 * PADP;

#pragma unroll 2
    for (int kt = 0; kt < 16; kt++) {
        int kk = kt * 8 + t4;
        uint32_t a0 = __float_as_uint(phiR0[kk]);
        uint32_t a1 = __float_as_uint(phiR1[kk]);
        uint32_t a2 = __float_as_uint(phiR0[kk + 4]);
        uint32_t a3 = __float_as_uint(phiR1[kk + 4]);
        uint32_t e1 = (uint32_t)ploR0[kk] << 16;
        uint32_t e2 = (uint32_t)ploR1[kk] << 16;
        uint32_t e3 = (uint32_t)ploR0[kk + 4] << 16;
        uint32_t e4 = (uint32_t)ploR1[kk + 4] << 16;
#pragma unroll
        for (int nt = 0; nt < 16; nt++) {
            int n = nt * 8 + grp;
            uint32_t b0 = __float_as_uint(sWhi[n * PADP + kk]);
            uint32_t b1 = __float_as_uint(sWhi[n * PADP + kk + 4]);
            uint32_t c0 = (uint32_t)sWlo[n * PADP + kk] << 16;
            uint32_t c1 = (uint32_t)sWlo[n * PADP + kk + 4] << 16;
            float* D = acc + nt * 4;
            MMA_TF32(D, a0, a1, a2, a3, b0, b1);     // hi*hi
            MMA_TF32(D, a0, a1, a2, a3, c0, c1);     // hi*lo
            MMA_TF32(D, e1, e2, e3, e4, b0, b1);     // lo*hi
        }
    }
    __syncthreads();                                 // all sPhi/sPlo reads done

    // ---- phase 4: tanh, stage to smem ----
#pragma unroll
    for (int nt = 0; nt < 16; nt++) {
        int col = nt * 8 + 2 * t4;
        float2 v0 = make_float2(fast_tanh(acc[nt * 4 + 0]), fast_tanh(acc[nt * 4 + 1]));
        float2 v1 = make_float2(fast_tanh(acc[nt * 4 + 2]), fast_tanh(acc[nt * 4 + 3]));
        *(float2*)&sPhi[m0 * PADP + col] = v0;
        *(float2*)&sPhi[(m0 + 8) * PADP + col] = v1;
    }
    __syncthreads();

    // ---- phase 5: vectorized scatter-add into C2[dst] ----
    for (int i = t; i < TE * 32; i += 256) {
        int e = i >> 5, c4 = i & 31;
        float4 v = *(float4*)&sPhi[e * PADP + c4 * 4];
        float* ptr = C2 + (size_t)sDst[e] * BASIS + c4 * 4;
        asm volatile("red.global.add.v4.f32 [%0], {%1,%2,%3,%4};"
                     :: "l"(ptr), "f"(v.x), "f"(v.y), "f"(v.z), "f"(v.w)
                     : "memory");
    }
}

// ---------------- K5: readout + pool ----------------
__global__ __launch_bounds__(256) void k_readout(const float* __restrict__ r1W,
                                                 const float* __restrict__ r1b,
                                                 const float* __restrict__ r2W,
                                                 const float* __restrict__ r2b,
                                                 const int* __restrict__ batch,
                                                 float* __restrict__ out, int sb) {
    extern __shared__ float sm[];
    float* sW1 = sm;                   // [256][128]
    float* sC  = sW1 + 32768;          // [32][132]
    float* sW2 = sC + 32 * 132;        // [4][256]
    float* sB1 = sW2 + 1024;           // [256]
    float* sAcc = sB1 + 256;           // [32][4]
    int*   sBat = (int*)(sAcc + 128);  // [32]
    const float* C = g_C[sb];
    int t = threadIdx.x, n0 = blockIdx.x * 32;

    for (int i = t; i < 8192; i += 256)
        ((float4*)sW1)[i] = ((const float4*)r1W)[i];
    if (t < 256) ((float4*)sW2)[t] = ((const float4*)r2W)[t];
    sB1[t] = r1b[t];
    if (t < 128) sAcc[t] = 0.f;
    if (t < 32)  sBat[t] = batch[n0 + t];
    for (int i = t; i < 32 * 32; i += 256) {
        int n = i >> 5, c4 = i & 31;
        *(float4*)&sC[n * 132 + c4 * 4] = ((const float4*)C)[(size_t)(n0 + n) * 32 + c4];
    }
    __syncthreads();

    int tx = t & 7, ty = t >> 3;
    float acc[4][8];
#pragma unroll
    for (int ii = 0; ii < 4; ii++)
#pragma unroll
        for (int jj = 0; jj < 8; jj++) acc[ii][jj] = 0.f;

#pragma unroll 2
    for (int c = 0; c < 128; c += 4) {
        float4 cv[4], wv[8];
#pragma unroll
        for (int ii = 0; ii < 4; ii++) cv[ii] = *(float4*)&sC[(tx + 8 * ii) * 132 + c];
#pragma unroll
        for (int jj = 0; jj < 8; jj++) wv[jj] = *(float4*)&sW1[(ty * 8 + jj) * 128 + c];
#pragma unroll
        for (int ii = 0; ii < 4; ii++)
#pragma unroll
            for (int jj = 0; jj < 8; jj++) {
                acc[ii][jj] = fmaf(cv[ii].x, wv[jj].x, acc[ii][jj]);
                acc[ii][jj] = fmaf(cv[ii].y, wv[jj].y, acc[ii][jj]);
                acc[ii][jj] = fmaf(cv[ii].z, wv[jj].z, acc[ii][jj]);
                acc[ii][jj] = fmaf(cv[ii].w, wv[jj].w, acc[ii][jj]);
            }
    }
    float po[4][4];
#pragma unroll
    for (int ii = 0; ii < 4; ii++)
#pragma unroll
        for (int o = 0; o < 4; o++) po[ii][o] = (ty == 0) ? r2b[o] : 0.f;
#pragma unroll
    for (int ii = 0; ii < 4; ii++)
#pragma unroll
        for (int jj = 0; jj < 8; jj++) {
            float h = fast_tanh(acc[ii][jj] + sB1[ty * 8 + jj]);
#pragma unroll
            for (int o = 0; o < 4; o++)
                po[ii][o] = fmaf(h, sW2[o * 256 + ty * 8 + jj], po[ii][o]);
        }
#pragma unroll
    for (int ii = 0; ii < 4; ii++)
#pragma unroll
        for (int o = 0; o < 4; o++)
            atomicAdd(&sAcc[(tx + 8 * ii) * 4 + o], po[ii][o]);
    __syncthreads();
    if (t < 128) {
        int n = t >> 2, o = t & 3;
        atomicAdd(&out[(size_t)sBat[n] * 4 + o], sAcc[t]);
    }
}

// ---------------- launch ----------------
extern "C" void kernel_launch(void* const* d_in, const int* in_sizes, int n_in,
                              void* d_out, int out_size) {
    const int*   Z         = (const int*)d_in[0];
    const int*   edge_index= (const int*)d_in[1];
    const float* edge_attr = (const float*)d_in[2];
    const int*   batch     = (const int*)d_in[3];
    const float* embed     = (const float*)d_in[4];
    const float* cfW       = (const float*)d_in[5];
    const float* cfb       = (const float*)d_in[6];
    const float* dfW       = (const float*)d_in[7];
    const float* dfb       = (const float*)d_in[8];
    const float* fcW       = (const float*)d_in[9];
    const float* r1W       = (const float*)d_in[10];
    const float* r1b       = (const float*)d_in[11];
    const float* r2W       = (const float*)d_in[12];
    const float* r2b       = (const float*)d_in[13];
    float* out = (float*)d_out;

    const int smK2 = (128 * 64 + 64 * 68 + 128) * 4;                      // 50688
    const int smK3 = (16384 + 32 * 132 + 128) * 4;                        // 82944
    const int smK4 = 2 * 128 * PADP * 4 + 2 * 128 * PADP * 2 + 2 * TE * 4; // 203776
    const int smK5 = (32768 + 32 * 132 + 1024 + 256 + 128) * 4 + 32 * 4;  // 153728

    cudaFuncSetAttribute(k_dfeat,   cudaFuncAttributeMaxDynamicSharedMemorySize, smK2);
    cudaFuncSetAttribute(k_node,    cudaFuncAttributeMaxDynamicSharedMemorySize, smK3);
    cudaFuncSetAttribute(k_edge,    cudaFuncAttributeMaxDynamicSharedMemorySize, smK4);
    cudaFuncSetAttribute(k_readout, cudaFuncAttributeMaxDynamicSharedMemorySize, smK5);

    k_zero<<<1, 256>>>(out);
    k_init<<<(N_NODES * 32) / 256, 256>>>(Z, embed);
    k_dfeat<<<N_EDGES / 64, 256, smK2>>>(edge_attr, dfW, dfb);

    int sb = 0;
    for (int it = 0; it < 3; it++) {
        k_node<<<N_NODES / 32, 256, smK3>>>(cfW, cfb, sb);
        k_edge<<<N_EDGES / TE, 256, smK4>>>(edge_index, fcW, sb ^ 1);
        sb ^= 1;
    }
    k_readout<<<N_NODES / 32, 256, smK5>>>(r1W, r1b, r2W, r2b, batch, out, sb);
}

// round 4
// speedup vs baseline: 1.3914x; 1.1812x over previous
#include <cuda_runtime.h>
#include <cuda_bf16.h>
#include <cstdint>

#define N_NODES   20000
#define N_EDGES   640000
#define BASIS     128
#define NUM_GAUSS 64
#define HIDDEN    256
#define NUM_GRAPHS 256

// ---------------- scratch (device globals: allocation-free rule) ----------------
__device__ float g_dfeat[(size_t)N_EDGES * BASIS];   // 327 MB, iteration-invariant
__device__ float g_C[2][(size_t)N_NODES * BASIS];    // ping-pong node states
__device__ float g_Cc[(size_t)N_NODES * BASIS];      // per-iter node transform

__device__ __forceinline__ float fast_tanh(float x) {
    float xc = fminf(fmaxf(x, -9.0f), 9.0f);
    float e  = __expf(2.0f * xc);
    return __fdividef(e - 1.0f, e + 1.0f);
}

// bf16 Dekker split: x = hi + lo (+O(2^-18))
__device__ __forceinline__ void split_bf16(float x, uint16_t& h, uint16_t& l) {
    __nv_bfloat16 hb = __float2bfloat16_rn(x);
    float hf = __bfloat162float(hb);
    __nv_bfloat16 lb = __float2bfloat16_rn(x - hf);
    h = __bfloat16_as_ushort(hb);
    l = __bfloat16_as_ushort(lb);
}

#define MMA_BF16(D, a0, a1, a2, a3, b0, b1)                                    \
    asm volatile("mma.sync.aligned.m16n8k16.row.col.f32.bf16.bf16.f32 "        \
                 "{%0,%1,%2,%3}, {%4,%5,%6,%7}, {%8,%9}, {%0,%1,%2,%3};"       \
                 : "+f"((D)[0]), "+f"((D)[1]), "+f"((D)[2]), "+f"((D)[3])      \
                 : "r"(a0), "r"(a1), "r"(a2), "r"(a3), "r"(b0), "r"(b1))

#define LDSM_X4(r0, r1, r2, r3, addr)                                          \
    asm volatile("ldmatrix.sync.aligned.m8n8.x4.shared.b16 {%0,%1,%2,%3}, [%4];" \
                 : "=r"(r0), "=r"(r1), "=r"(r2), "=r"(r3) : "r"(addr))

#define LDSM_X2(r0, r1, addr)                                                  \
    asm volatile("ldmatrix.sync.aligned.m8n8.x2.shared.b16 {%0,%1}, [%2];"     \
                 : "=r"(r0), "=r"(r1) : "r"(addr))

// ---------------- K0: zero output ----------------
__global__ void k_zero(float* __restrict__ out) {
    ((float4*)out)[threadIdx.x] = make_float4(0.f, 0.f, 0.f, 0.f);
}

// ---------------- K1: C0 = embed[Z] ----------------
__global__ __launch_bounds__(256) void k_init(const int* __restrict__ Z,
                                              const float* __restrict__ embed) {
    int idx = blockIdx.x * 256 + threadIdx.x;
    int v = idx >> 5, c4 = idx & 31;
    float4 val = ((const float4*)embed)[(size_t)Z[v] * 32 + c4];
    ((float4*)g_C[0])[idx] = val;
}

// ---------------- K2: d_feat = edge_attr @ dfW.T + dfb  [E,128] ----------------
__global__ __launch_bounds__(256) void k_dfeat(const float* __restrict__ edge_attr,
                                               const float* __restrict__ dfW,
                                               const float* __restrict__ dfb) {
    extern __shared__ float sm[];
    float* sW = sm;                  // [128][64]
    float* sA = sm + 128 * 64;       // [64][68]
    float* sB = sA + 64 * 68;        // [128]
    int t = threadIdx.x;
    int e0 = blockIdx.x * 64;

    for (int i = t; i < 2048; i += 256)
        ((float4*)sW)[i] = ((const float4*)dfW)[i];
    if (t < 128) sB[t] = dfb[t];
    for (int i = t; i < 64 * 16; i += 256) {
        int e = i >> 4, g4 = i & 15;
        float4 v = ((const float4*)edge_attr)[(size_t)(e0 + e) * 16 + g4];
        *(float4*)&sA[e * 68 + g4 * 4] = v;
    }
    __syncthreads();

    int tx = t & 7, ty = t >> 3;
    float acc[8][4];
#pragma unroll
    for (int ii = 0; ii < 8; ii++)
#pragma unroll
        for (int jj = 0; jj < 4; jj++) acc[ii][jj] = 0.f;

#pragma unroll 4
    for (int k = 0; k < 64; k += 4) {
        float4 av[8], wv[4];
#pragma unroll
        for (int ii = 0; ii < 8; ii++) av[ii] = *(float4*)&sA[(tx + 8 * ii) * 68 + k];
#pragma unroll
        for (int jj = 0; jj < 4; jj++) wv[jj] = *(float4*)&sW[(ty * 4 + jj) * 64 + k];
#pragma unroll
        for (int ii = 0; ii < 8; ii++)
#pragma unroll
            for (int jj = 0; jj < 4; jj++) {
                acc[ii][jj] = fmaf(av[ii].x, wv[jj].x, acc[ii][jj]);
                acc[ii][jj] = fmaf(av[ii].y, wv[jj].y, acc[ii][jj]);
                acc[ii][jj] = fmaf(av[ii].z, wv[jj].z, acc[ii][jj]);
                acc[ii][jj] = fmaf(av[ii].w, wv[jj].w, acc[ii][jj]);
            }
    }
    float4 bb = *(float4*)&sB[ty * 4];
#pragma unroll
    for (int ii = 0; ii < 8; ii++) {
        float4 o = make_float4(acc[ii][0] + bb.x, acc[ii][1] + bb.y,
                               acc[ii][2] + bb.z, acc[ii][3] + bb.w);
        ((float4*)g_dfeat)[(size_t)(e0 + tx + 8 * ii) * 32 + ty] = o;
    }
}

// ---------------- K3: Cc = C@cfW.T + cfb ; C2 = C ----------------
__global__ __launch_bounds__(256) void k_node(const float* __restrict__ cfW,
                                              const float* __restrict__ cfb,
                                              int sb) {
    extern __shared__ float sm[];
    float* sW = sm;                  // [128][128]
    float* sC = sm + 16384;          // [32][132]
    float* sBb = sC + 32 * 132;      // [128]
    const float* C = g_C[sb];
    float* C2 = g_C[sb ^ 1];
    int t = threadIdx.x, n0 = blockIdx.x * 32;

    for (int i = t; i < 4096; i += 256)
        ((float4*)sW)[i] = ((const float4*)cfW)[i];
    if (t < 128) sBb[t] = cfb[t];
    for (int i = t; i < 32 * 32; i += 256) {
        int n = i >> 5, c4 = i & 31;
        *(float4*)&sC[n * 132 + c4 * 4] = ((const float4*)C)[(size_t)(n0 + n) * 32 + c4];
    }
    __syncthreads();

    int tx = t & 7, ty = t >> 3;
    float acc[4][4];
#pragma unroll
    for (int ii = 0; ii < 4; ii++)
#pragma unroll
        for (int jj = 0; jj < 4; jj++) acc[ii][jj] = 0.f;

#pragma unroll 4
    for (int k = 0; k < 128; k += 4) {
        float4 cv[4], wv[4];
#pragma unroll
        for (int ii = 0; ii < 4; ii++) cv[ii] = *(float4*)&sC[(tx + 8 * ii) * 132 + k];
#pragma unroll
        for (int jj = 0; jj < 4; jj++) wv[jj] = *(float4*)&sW[(ty * 4 + jj) * 128 + k];
#pragma unroll
        for (int ii = 0; ii < 4; ii++)
#pragma unroll
            for (int jj = 0; jj < 4; jj++) {
                acc[ii][jj] = fmaf(cv[ii].x, wv[jj].x, acc[ii][jj]);
                acc[ii][jj] = fmaf(cv[ii].y, wv[jj].y, acc[ii][jj]);
                acc[ii][jj] = fmaf(cv[ii].z, wv[jj].z, acc[ii][jj]);
                acc[ii][jj] = fmaf(cv[ii].w, wv[jj].w, acc[ii][jj]);
            }
    }
    float4 bb = *(float4*)&sBb[ty * 4];
#pragma unroll
    for (int ii = 0; ii < 4; ii++) {
        float4 o = make_float4(acc[ii][0] + bb.x, acc[ii][1] + bb.y,
                               acc[ii][2] + bb.z, acc[ii][3] + bb.w);
        ((float4*)g_Cc)[(size_t)(n0 + tx + 8 * ii) * 32 + ty] = o;
    }
    for (int i = t; i < 32 * 32; i += 256) {
        int n = i >> 5, c4 = i & 31;
        ((float4*)C2)[(size_t)(n0 + n) * 32 + c4] = *(float4*)&sC[n * 132 + c4 * 4];
    }
}

// ---------------- K4 (hot): m = tanh((Cc[src]*d_feat)@fcW.T); C2[dst] += m ------
// bf16 2-term Dekker split, mma.m16n8k16, ldmatrix operands.
// TE=128 edges/block, 256 threads (8 warps), warp grid 4x2 (32m x 64n tiles).
#define TE  128
#define PB  136   // bf16 row stride (272 B): conflict-free ldmatrix
#define POS 132   // f32 output staging stride
__global__ __launch_bounds__(256) void k_edge(const int* __restrict__ edge_index,
                                              const float* __restrict__ fcW,
                                              int db) {
    extern __shared__ char smraw[];
    uint16_t* sWhi = (uint16_t*)smraw;               // [128][136] bf16
    uint16_t* sWlo = sWhi + 128 * PB;
    uint16_t* sPhi = sWlo + 128 * PB;                // [128][136] bf16
    uint16_t* sPlo = sPhi + 128 * PB;
    int* sSrc = (int*)(sPlo + 128 * PB);
    int* sDst = sSrc + TE;
    float* sOut = (float*)sPhi;                      // overwrites P after MMA
    float* C2 = g_C[db];
    int t = threadIdx.x, e0 = blockIdx.x * TE;

    // ---- phase 1: stage & split W; load indices ----
    for (int i = t; i < 4096; i += 256) {            // float4 over fcW
        int n = i >> 5, k4 = i & 31;
        float4 w = ((const float4*)fcW)[i];
        uint16_t h0, h1, h2, h3, l0, l1, l2, l3;
        split_bf16(w.x, h0, l0); split_bf16(w.y, h1, l1);
        split_bf16(w.z, h2, l2); split_bf16(w.w, h3, l3);
        *(uint2*)&sWhi[n * PB + k4 * 4] =
            make_uint2((uint32_t)h0 | ((uint32_t)h1 << 16), (uint32_t)h2 | ((uint32_t)h3 << 16));
        *(uint2*)&sWlo[n * PB + k4 * 4] =
            make_uint2((uint32_t)l0 | ((uint32_t)l1 << 16), (uint32_t)l2 | ((uint32_t)l3 << 16));
    }
    if (t < TE)          sSrc[t]      = edge_index[e0 + t];
    else if (t < 2 * TE) sDst[t - TE] = edge_index[N_EDGES + e0 + (t - TE)];
    __syncthreads();

    // ---- phase 2: build & split P = Cc[src] * d_feat ----
    for (int i = t; i < TE * 32; i += 256) {
        int e = i >> 5, c4 = i & 31;
        float4 d = ((const float4*)g_dfeat)[(size_t)(e0 + e) * 32 + c4];
        float4 c = ((const float4*)g_Cc)[(size_t)sSrc[e] * 32 + c4];
        float4 p = make_float4(d.x * c.x, d.y * c.y, d.z * c.z, d.w * c.w);
        uint16_t h0, h1, h2, h3, l0, l1, l2, l3;
        split_bf16(p.x, h0, l0); split_bf16(p.y, h1, l1);
        split_bf16(p.z, h2, l2); split_bf16(p.w, h3, l3);
        *(uint2*)&sPhi[e * PB + c4 * 4] =
            make_uint2((uint32_t)h0 | ((uint32_t)h1 << 16), (uint32_t)h2 | ((uint32_t)h3 << 16));
        *(uint2*)&sPlo[e * PB + c4 * 4] =
            make_uint2((uint32_t)l0 | ((uint32_t)l1 << 16), (uint32_t)l2 | ((uint32_t)l3 << 16));
    }
    __syncthreads();

    // ---- phase 3: bf16 split tensor GEMM  D[128x128] = P @ W^T ----
    const int lane = t & 31, wid = t >> 5;
    const int mbase = (wid >> 1) * 32;               // 4 warp rows x 32
    const int nbase = (wid & 1) * 64;                // 2 warp cols x 64
    // ldmatrix per-lane row offsets (elements)
    const int aoff = (mbase + (lane & 15)) * PB + ((lane & 16) ? 8 : 0);
    const int boff = (nbase + (lane & 7)) * PB + ((lane & 8) ? 8 : 0);
    const uint32_t sPhiA = (uint32_t)__cvta_generic_to_shared(sPhi);
    const uint32_t sPloA = (uint32_t)__cvta_generic_to_shared(sPlo);
    const uint32_t sWhiA = (uint32_t)__cvta_generic_to_shared(sWhi);
    const uint32_t sWloA = (uint32_t)__cvta_generic_to_shared(sWlo);

    float acc[64];                                   // [mt2][nt8][4]
#pragma unroll
    for (int i = 0; i < 64; i++) acc[i] = 0.f;

#pragma unroll
    for (int kt = 0; kt < 8; kt++) {
        uint32_t ahi[2][4], alo[2][4];
#pragma unroll
        for (int mt = 0; mt < 2; mt++) {
            uint32_t off = (uint32_t)(aoff + mt * 16 * PB + kt * 16) * 2;
            LDSM_X4(ahi[mt][0], ahi[mt][1], ahi[mt][2], ahi[mt][3], sPhiA + off);
            LDSM_X4(alo[mt][0], alo[mt][1], alo[mt][2], alo[mt][3], sPloA + off);
        }
#pragma unroll
        for (int nt = 0; nt < 8; nt++) {
            uint32_t off = (uint32_t)(boff + nt * 8 * PB + kt * 16) * 2;
            uint32_t bh0, bh1, bl0, bl1;
            LDSM_X2(bh0, bh1, sWhiA + off);
            LDSM_X2(bl0, bl1, sWloA + off);
#pragma unroll
            for (int mt = 0; mt < 2; mt++) {
                float* D = acc + (mt * 8 + nt) * 4;
                MMA_BF16(D, ahi[mt][0], ahi[mt][1], ahi[mt][2], ahi[mt][3], bh0, bh1);
                MMA_BF16(D, ahi[mt][0], ahi[mt][1], ahi[mt][2], ahi[mt][3], bl0, bl1);
                MMA_BF16(D, alo[mt][0], alo[mt][1], alo[mt][2], alo[mt][3], bh0, bh1);
            }
        }
    }
    __syncthreads();                                 // all P/W reads done

    // ---- phase 4: tanh, stage f32 to smem (overwrites P region) ----
    const int grp = lane >> 2, t4 = lane & 3;
#pragma unroll
    for (int mt = 0; mt < 2; mt++)
#pragma unroll
        for (int nt = 0; nt < 8; nt++) {
            int m = mbase + mt * 16 + grp;
            int n = nbase + nt * 8 + 2 * t4;
            const float* D = acc + (mt * 8 + nt) * 4;
            *(float2*)&sOut[m * POS + n] = make_float2(fast_tanh(D[0]), fast_tanh(D[1]));
            *(float2*)&sOut[(m + 8) * POS + n] = make_float2(fast_tanh(D[2]), fast_tanh(D[3]));
        }
    __syncthreads();

    // ---- phase 5: vectorized scatter-add into C2[dst] ----
    for (int i = t; i < TE * 32; i += 256) {
        int e = i >> 5, c4 = i & 31;
        float4 v = *(float4*)&sOut[e * POS + c4 * 4];
        float* ptr = C2 + (size_t)sDst[e] * BASIS + c4 * 4;
        asm volatile("red.global.add.v4.f32 [%0], {%1,%2,%3,%4};"
                     :: "l"(ptr), "f"(v.x), "f"(v.y), "f"(v.z), "f"(v.w)
                     : "memory");
    }
}

// ---------------- K5: readout + pool ----------------
__global__ __launch_bounds__(256) void k_readout(const float* __restrict__ r1W,
                                                 const float* __restrict__ r1b,
                                                 const float* __restrict__ r2W,
                                                 const float* __restrict__ r2b,
                                                 const int* __restrict__ batch,
                                                 float* __restrict__ out, int sb) {
    extern __shared__ float sm[];
    float* sW1 = sm;                   // [256][128]
    float* sC  = sW1 + 32768;          // [32][132]
    float* sW2 = sC + 32 * 132;        // [4][256]
    float* sB1 = sW2 + 1024;           // [256]
    float* sAcc = sB1 + 256;           // [32][4]
    int*   sBat = (int*)(sAcc + 128);  // [32]
    const float* C = g_C[sb];
    int t = threadIdx.x, n0 = blockIdx.x * 32;

    for (int i = t; i < 8192; i += 256)
        ((float4*)sW1)[i] = ((const float4*)r1W)[i];
    if (t < 256) ((float4*)sW2)[t] = ((const float4*)r2W)[t];
    sB1[t] = r1b[t];
    if (t < 128) sAcc[t] = 0.f;
    if (t < 32)  sBat[t] = batch[n0 + t];
    for (int i = t; i < 32 * 32; i += 256) {
        int n = i >> 5, c4 = i & 31;
        *(float4*)&sC[n * 132 + c4 * 4] = ((const float4*)C)[(size_t)(n0 + n) * 32 + c4];
    }
    __syncthreads();

    int tx = t & 7, ty = t >> 3;
    float acc[4][8];
#pragma unroll
    for (int ii = 0; ii < 4; ii++)
#pragma unroll
        for (int jj = 0; jj < 8; jj++) acc[ii][jj] = 0.f;

#pragma unroll 2
    for (int c = 0; c < 128; c += 4) {
        float4 cv[4], wv[8];
#pragma unroll
        for (int ii = 0; ii < 4; ii++) cv[ii] = *(float4*)&sC[(tx + 8 * ii) * 132 + c];
#pragma unroll
        for (int jj = 0; jj < 8; jj++) wv[jj] = *(float4*)&sW1[(ty * 8 + jj) * 128 + c];
#pragma unroll
        for (int ii = 0; ii < 4; ii++)
#pragma unroll
            for (int jj = 0; jj < 8; jj++) {
                acc[ii][jj] = fmaf(cv[ii].x, wv[jj].x, acc[ii][jj]);
                acc[ii][jj] = fmaf(cv[ii].y, wv[jj].y, acc[ii][jj]);
                acc[ii][jj] = fmaf(cv[ii].z, wv[jj].z, acc[ii][jj]);
                acc[ii][jj] = fmaf(cv[ii].w, wv[jj].w, acc[ii][jj]);
            }
    }
    float po[4][4];
#pragma unroll
    for (int ii = 0; ii < 4; ii++)
#pragma unroll
        for (int o = 0; o < 4; o++) po[ii][o] = (ty == 0) ? r2b[o] : 0.f;
#pragma unroll
    for (int ii = 0; ii < 4; ii++)
#pragma unroll
        for (int jj = 0; jj < 8; jj++) {
            float h = fast_tanh(acc[ii][jj] + sB1[ty * 8 + jj]);
#pragma unroll
            for (int o = 0; o < 4; o++)
                po[ii][o] = fmaf(h, sW2[o * 256 + ty * 8 + jj], po[ii][o]);
        }
#pragma unroll
    for (int ii = 0; ii < 4; ii++)
#pragma unroll
        for (int o = 0; o < 4; o++)
            atomicAdd(&sAcc[(tx + 8 * ii) * 4 + o], po[ii][o]);
    __syncthreads();
    if (t < 128) {
        int n = t >> 2, o = t & 3;
        atomicAdd(&out[(size_t)sBat[n] * 4 + o], sAcc[t]);
    }
}

// ---------------- launch ----------------
extern "C" void kernel_launch(void* const* d_in, const int* in_sizes, int n_in,
                              void* d_out, int out_size) {
    const int*   Z         = (const int*)d_in[0];
    const int*   edge_index= (const int*)d_in[1];
    const float* edge_attr = (const float*)d_in[2];
    const int*   batch     = (const int*)d_in[3];
    const float* embed     = (const float*)d_in[4];
    const float* cfW       = (const float*)d_in[5];
    const float* cfb       = (const float*)d_in[6];
    const float* dfW       = (const float*)d_in[7];
    const float* dfb       = (const float*)d_in[8];
    const float* fcW       = (const float*)d_in[9];
    const float* r1W       = (const float*)d_in[10];
    const float* r1b       = (const float*)d_in[11];
    const float* r2W       = (const float*)d_in[12];
    const float* r2b       = (const float*)d_in[13];
    float* out = (float*)d_out;

    const int smK2 = (128 * 64 + 64 * 68 + 128) * 4;                      // 50688
    const int smK3 = (16384 + 32 * 132 + 128) * 4;                        // 82944
    const int smK4 = 4 * 128 * PB * 2 + 2 * TE * 4;                       // 140288
    const int smK5 = (32768 + 32 * 132 + 1024 + 256 + 128) * 4 + 32 * 4;  // 153728

    cudaFuncSetAttribute(k_dfeat,   cudaFuncAttributeMaxDynamicSharedMemorySize, smK2);
    cudaFuncSetAttribute(k_node,    cudaFuncAttributeMaxDynamicSharedMemorySize, smK3);
    cudaFuncSetAttribute(k_edge,    cudaFuncAttributeMaxDynamicSharedMemorySize, smK4);
    cudaFuncSetAttribute(k_readout, cudaFuncAttributeMaxDynamicSharedMemorySize, smK5);

    k_zero<<<1, 256>>>(out);
    k_init<<<(N_NODES * 32) / 256, 256>>>(Z, embed);
    k_dfeat<<<N_EDGES / 64, 256, smK2>>>(edge_attr, dfW, dfb);

    int sb = 0;
    for (int it = 0; it < 3; it++) {
        k_node<<<N_NODES / 32, 256, smK3>>>(cfW, cfb, sb);
        k_edge<<<N_EDGES / TE, 256, smK4>>>(edge_index, fcW, sb ^ 1);
        sb ^= 1;
    }
    k_readout<<<N_NODES / 32, 256, smK5>>>(r1W, r1b, r2W, r2b, batch, out, sb);
}